// round 9
// baseline (speedup 1.0000x reference)
#include <cuda_runtime.h>

// HardLinearAttention — algebraic collapse of P@Z@M@Z^T@Q@Z.
// d=1024, n=8192, Z is (2d+1, n+1) = (2049, 8193) float32.
//
//   v[j]  = sum_{k<8192} Z[j,k] * Z[2048,k]          (j < 1024)
//   r[k]  = sum_{j<1024} v[j] * (Z[1024+j,k] - Z[j,k])
//   out   = Z;  out[2048,k] += (alpha/8192) * r[k]

#define D       1024
#define NCOLS   8192
#define S       8193          // n+1 (row stride)
#define JCHUNKS 16
#define JPER    (D / JCHUNKS) // 64
#define UN      8             // k1 load-batch depth (24 LDGs per batch)

__device__ float g_v[D];
__device__ float g_part[JCHUNKS * S];

// Volatile global load: ptxas cannot sink/fuse it into the FMA stream, so a
// run of these issues back-to-back -> true front-batched MLP.
__device__ __forceinline__ float ldg_v(const float* p) {
    float r;
    asm volatile("ld.global.f32 %0, [%1];" : "=f"(r) : "l"(p));
    return r;
}

// ---------------- kernel 1: v[j] = dot(Z[j, 0:8192], Z[2048, 0:8192]) ----
// Block b handles rows {b, b+512}. 24 independent volatile LDGs per batch
// keep ~24 cache lines in flight per warp (vs ~2 when ptxas interleaves).
__global__ void __launch_bounds__(256) k_compute_v(const float* __restrict__ Z) {
    const int b = blockIdx.x;                       // 0..511
    const float* __restrict__ ra = Z + (size_t)b * S;
    const float* __restrict__ rb = Z + (size_t)(b + 512) * S;
    const float* __restrict__ u  = Z + (size_t)2048 * S;

    float acc0 = 0.f, acc1 = 0.f;

    // 8192 cols / 256 threads = 32 iters = 4 batches of UN=8. Exact fit.
    for (int k0 = threadIdx.x; k0 < NCOLS; k0 += 256 * UN) {
        float ua[UN], za[UN], zb[UN];
        #pragma unroll
        for (int s = 0; s < UN; s++) ua[s] = ldg_v(u  + k0 + 256 * s);
        #pragma unroll
        for (int s = 0; s < UN; s++) za[s] = ldg_v(ra + k0 + 256 * s);
        #pragma unroll
        for (int s = 0; s < UN; s++) zb[s] = ldg_v(rb + k0 + 256 * s);
        #pragma unroll
        for (int s = 0; s < UN; s++) {
            acc0 += za[s] * ua[s];
            acc1 += zb[s] * ua[s];
        }
    }

    // block reduce (two values)
    #pragma unroll
    for (int o = 16; o > 0; o >>= 1) {
        acc0 += __shfl_down_sync(0xffffffffu, acc0, o);
        acc1 += __shfl_down_sync(0xffffffffu, acc1, o);
    }
    __shared__ float s0[8], s1[8];
    const int lane = threadIdx.x & 31;
    const int w    = threadIdx.x >> 5;
    if (lane == 0) { s0[w] = acc0; s1[w] = acc1; }
    __syncthreads();
    if (w == 0) {
        acc0 = (lane < 8) ? s0[lane] : 0.f;
        acc1 = (lane < 8) ? s1[lane] : 0.f;
        #pragma unroll
        for (int o = 4; o > 0; o >>= 1) {
            acc0 += __shfl_down_sync(0xffffffffu, acc0, o);
            acc1 += __shfl_down_sync(0xffffffffu, acc1, o);
        }
        if (lane == 0) { g_v[b] = acc0; g_v[b + 512] = acc1; }
    }
}

// ---------------- kernel 2: copy rows 0..2047 + partial r accumulation ---
// grid = (ceil(S/256), JCHUNKS); each thread owns one column k.
// Unchanged (already ~5.5 TB/s effective).
__global__ void __launch_bounds__(256) k_copy_acc(const float* __restrict__ Z,
                                                  float* __restrict__ out) {
    const int jc = blockIdx.y;
    const int k  = blockIdx.x * 256 + threadIdx.x;

    __shared__ float vs[JPER];
    if (threadIdx.x < JPER) vs[threadIdx.x] = g_v[jc * JPER + threadIdx.x];
    __syncthreads();

    if (k >= S) return;

    const int j0 = jc * JPER;
    float acc = 0.f;
    #pragma unroll 8
    for (int jj = 0; jj < JPER; jj++) {
        const size_t ia = (size_t)(j0 + jj) * S + k;
        const size_t ib = (size_t)(j0 + jj + D) * S + k;
        const float a = Z[ia];
        const float b = Z[ib];
        out[ia] = a;
        out[ib] = b;
        acc += vs[jj] * (b - a);
    }
    g_part[(size_t)jc * S + k] = acc;
}

// ---------------- kernel 3: reduce partials, write final row 2048 --------
__global__ void __launch_bounds__(256) k_final(const float* __restrict__ Z,
                                               const float* __restrict__ alpha,
                                               float* __restrict__ out) {
    const int k = blockIdx.x * 256 + threadIdx.x;
    if (k >= S) return;
    float sum = 0.f;
    #pragma unroll
    for (int jc = 0; jc < JCHUNKS; jc++)
        sum += g_part[(size_t)jc * S + k];
    const float scale = alpha[0] / (float)NCOLS;
    out[(size_t)2048 * S + k] = Z[(size_t)2048 * S + k] + scale * sum;
}

extern "C" void kernel_launch(void* const* d_in, const int* in_sizes, int n_in,
                              void* d_out, int out_size) {
    const float* Z     = (const float*)d_in[0];
    const float* alpha = (const float*)d_in[1];
    float* out         = (float*)d_out;

    k_compute_v<<<512, 256>>>(Z);

    dim3 g2((S + 255) / 256, JCHUNKS);
    k_copy_acc<<<g2, 256>>>(Z, out);

    k_final<<<(S + 255) / 256, 256>>>(Z, alpha, out);
}